// round 15
// baseline (speedup 1.0000x reference)
#include <cuda_runtime.h>
#include <cuda_bf16.h>
#include <math.h>
#include <stdint.h>

// GCN1: 3-layer GCN over 4 graphs, shared weights, scalar-mean output.
// R15 = R14 resubmitted verbatim (container infra failure, kernel untested):
//      R11 baseline (best: 1348us) + ONE change: unroll-4 edge loop in the
//      fp32-gather SpMM (phase-wise to cap register pressure; MLP 6->12
//      outstanding LDG.128 per warp). Plus merged init/prep launches.
//      SpMM gathers fp32, emits bf16x2; GEMM is bf16 mma.sync; per-graph
//      launches (batching regressed in R13).

#define NN 50000
#define EE 800000
#define FH 304
#define FI 128
#define NG 4
#define NB 196   // ceil(NN/256)

// ---------------- scratch (__device__ only; never passed as kernel args) ----
__device__ __align__(128) uint32_t g_bufAh[(size_t)NN * 160]; // SpMM out bf16x2 (padded)
__device__ __align__(128) float    g_bufB[(size_t)NN * FH];   // GEMM out (fp32)
__device__ __align__(128) uint32_t g_Wh1[320 * 64];           // [Npad][K/2] bf16x2
__device__ __align__(128) uint32_t g_Wh2[320 * 160];
__device__ __align__(128) uint32_t g_Wh3[320 * 160];
__device__ float g_ns[NG][NN];
__device__ float g_nd[NG][NN];
__device__ int   g_deg_s[NG][NN];
__device__ int   g_deg_d[NG][NN];
__device__ int   g_rowoff[NG][NN + 1];
__device__ int   g_cursor[NG][NN];
__device__ int   g_csr[NG][EE];
__device__ int   g_bsum[NG][256];
__device__ int   g_boff[NG][256];
__device__ double g_sum;

// ---------------- helpers ----------------------------------------------------
__device__ __forceinline__ uint32_t packbf(float x, float y) {
    __nv_bfloat162 b = __float22bfloat162_rn(make_float2(x, y));
    return *(uint32_t*)&b;
}

// ---------------- setup: init + all 3 weight preps in ONE launch -------------
// blocks [0,80): W1 (Kp2=64); [80,280): W2 (Kp2=160); [280,480): W3 (Kp2=160)
__global__ void k_prep(const float* __restrict__ W1, const float* __restrict__ W2,
                       const float* __restrict__ W3) {
    if (blockIdx.x == 0 && threadIdx.x == 0) g_sum = 0.0;
    int Kp2, K, base;
    const float* W;
    uint32_t* dst;
    if (blockIdx.x < 80)       { Kp2 = 64;  K = 128; base = 0;   W = W1; dst = g_Wh1; }
    else if (blockIdx.x < 280) { Kp2 = 160; K = 304; base = 80;  W = W2; dst = g_Wh2; }
    else                       { Kp2 = 160; K = 304; base = 280; W = W3; dst = g_Wh3; }
    int id = (blockIdx.x - base) * blockDim.x + threadIdx.x;
    if (id >= 320 * Kp2) return;
    int n = id / Kp2, kw = id % Kp2;
    int k = 2 * kw;
    float v0 = (k < K && n < FH) ? W[(size_t)k * FH + n] : 0.f;
    float v1 = (k + 1 < K && n < FH) ? W[(size_t)(k + 1) * FH + n] : 0.f;
    dst[(size_t)n * Kp2 + kw] = packbf(v0, v1);
}

__global__ void k_zero() {
    int g = blockIdx.y;
    int i = blockIdx.x * blockDim.x + threadIdx.x;
    if (i < NN) { g_deg_s[g][i] = 0; g_deg_d[g][i] = 0; }
}

__global__ void k_deg(const int* __restrict__ s0, const int* __restrict__ d0,
                      const int* __restrict__ s1, const int* __restrict__ d1,
                      const int* __restrict__ s2, const int* __restrict__ d2,
                      const int* __restrict__ s3, const int* __restrict__ d3) {
    int g = blockIdx.y;
    const int* s = (g == 0) ? s0 : (g == 1) ? s1 : (g == 2) ? s2 : s3;
    const int* d = (g == 0) ? d0 : (g == 1) ? d1 : (g == 2) ? d2 : d3;
    int e = blockIdx.x * blockDim.x + threadIdx.x;
    if (e < EE) {
        atomicAdd(&g_deg_s[g][s[e]], 1);
        atomicAdd(&g_deg_d[g][d[e]], 1);
    }
}

__global__ void k_scan1() {
    int g = blockIdx.y, t = threadIdx.x;
    int i = blockIdx.x * 256 + t;
    __shared__ int sm[256];
    sm[t] = (i < NN) ? g_deg_d[g][i] : 0;
    __syncthreads();
    for (int o = 128; o > 0; o >>= 1) {
        if (t < o) sm[t] += sm[t + o];
        __syncthreads();
    }
    if (t == 0) g_bsum[g][blockIdx.x] = sm[0];
}

__global__ void k_scan2() {
    int g = blockIdx.y, t = threadIdx.x;
    int v = (t < NB) ? g_bsum[g][t] : 0;
    __shared__ int sm[256];
    sm[t] = v;
    __syncthreads();
    for (int o = 1; o < 256; o <<= 1) {
        int a = (t >= o) ? sm[t - o] : 0;
        __syncthreads();
        sm[t] += a;
        __syncthreads();
    }
    g_boff[g][t] = sm[t] - v;  // exclusive
}

__global__ void k_scan3() {
    int g = blockIdx.y, t = threadIdx.x;
    int i = blockIdx.x * 256 + t;
    int d = (i < NN) ? g_deg_d[g][i] : 0;
    __shared__ int sm[256];
    sm[t] = d;
    __syncthreads();
    for (int o = 1; o < 256; o <<= 1) {
        int a = (t >= o) ? sm[t - o] : 0;
        __syncthreads();
        sm[t] += a;
        __syncthreads();
    }
    int off = g_boff[g][blockIdx.x] + sm[t] - d;  // exclusive
    if (i < NN) {
        g_rowoff[g][i] = off;
        g_cursor[g][i] = off;
        g_nd[g][i] = rsqrtf((float)max(d, 1));
        g_ns[g][i] = rsqrtf((float)max(g_deg_s[g][i], 1));
    }
    if (blockIdx.x == 0 && t == 0) g_rowoff[g][NN] = EE;
}

__global__ void k_scatter(const int* __restrict__ s0, const int* __restrict__ d0,
                          const int* __restrict__ s1, const int* __restrict__ d1,
                          const int* __restrict__ s2, const int* __restrict__ d2,
                          const int* __restrict__ s3, const int* __restrict__ d3) {
    int g = blockIdx.y;
    const int* s = (g == 0) ? s0 : (g == 1) ? s1 : (g == 2) ? s2 : s3;
    const int* d = (g == 0) ? d0 : (g == 1) ? d1 : (g == 2) ? d2 : d3;
    int e = blockIdx.x * blockDim.x + threadIdx.x;
    if (e < EE) {
        int p = atomicAdd(&g_cursor[g][d[e]], 1);
        g_csr[g][p] = s[e];
    }
}

// Warp-per-dst SpMM, float4 gathers (fp32 rows), bf16x2 output.
// Unroll-4 edges, phase-wise loads (4 rows' float4s in flight per phase).
// Lane l owns float4 slots l, l+32 (F>128), l+64 (l<12).
__global__ void __launch_bounds__(256)
k_spmm(const float* __restrict__ xext, int use_ext, int F, int g, int wstride) {
    const float* __restrict__ hin = use_ext ? xext : (const float*)g_bufB;
    int n = blockIdx.x * 8 + (threadIdx.x >> 5);
    if (n >= NN) return;
    int lane = threadIdx.x & 31;
    int beg = g_rowoff[g][n];
    int end = g_rowoff[g][n + 1];
    float4 a0 = make_float4(0.f, 0.f, 0.f, 0.f);
    float4 a1 = make_float4(0.f, 0.f, 0.f, 0.f);
    float4 a2 = make_float4(0.f, 0.f, 0.f, 0.f);
    int j = beg;
    for (; j + 3 < end; j += 4) {
        int s0 = g_csr[g][j],     s1 = g_csr[g][j + 1];
        int s2 = g_csr[g][j + 2], s3 = g_csr[g][j + 3];
        float w0 = g_ns[g][s0], w1 = g_ns[g][s1];
        float w2 = g_ns[g][s2], w3 = g_ns[g][s3];
        const float4* r0 = (const float4*)(hin + (size_t)s0 * F);
        const float4* r1 = (const float4*)(hin + (size_t)s1 * F);
        const float4* r2 = (const float4*)(hin + (size_t)s2 * F);
        const float4* r3 = (const float4*)(hin + (size_t)s3 * F);
        {   // phase 1: slot lane
            float4 u0 = r0[lane], u1 = r1[lane], u2 = r2[lane], u3 = r3[lane];
            a0.x += w0 * u0.x + w1 * u1.x + w2 * u2.x + w3 * u3.x;
            a0.y += w0 * u0.y + w1 * u1.y + w2 * u2.y + w3 * u3.y;
            a0.z += w0 * u0.z + w1 * u1.z + w2 * u2.z + w3 * u3.z;
            a0.w += w0 * u0.w + w1 * u1.w + w2 * u2.w + w3 * u3.w;
        }
        if (F > 128) {
            {   // phase 2: slot lane+32
                float4 u0 = r0[lane + 32], u1 = r1[lane + 32];
                float4 u2 = r2[lane + 32], u3 = r3[lane + 32];
                a1.x += w0 * u0.x + w1 * u1.x + w2 * u2.x + w3 * u3.x;
                a1.y += w0 * u0.y + w1 * u1.y + w2 * u2.y + w3 * u3.y;
                a1.z += w0 * u0.z + w1 * u1.z + w2 * u2.z + w3 * u3.z;
                a1.w += w0 * u0.w + w1 * u1.w + w2 * u2.w + w3 * u3.w;
            }
            if (lane < 12) {  // phase 3: slot lane+64
                float4 u0 = r0[lane + 64], u1 = r1[lane + 64];
                float4 u2 = r2[lane + 64], u3 = r3[lane + 64];
                a2.x += w0 * u0.x + w1 * u1.x + w2 * u2.x + w3 * u3.x;
                a2.y += w0 * u0.y + w1 * u1.y + w2 * u2.y + w3 * u3.y;
                a2.z += w0 * u0.z + w1 * u1.z + w2 * u2.z + w3 * u3.z;
                a2.w += w0 * u0.w + w1 * u1.w + w2 * u2.w + w3 * u3.w;
            }
        }
    }
    for (; j < end; j++) {
        int s = g_csr[g][j];
        float w = g_ns[g][s];
        const float4* r = (const float4*)(hin + (size_t)s * F);
        float4 u = r[lane];
        a0.x += w * u.x;  a0.y += w * u.y;  a0.z += w * u.z;  a0.w += w * u.w;
        if (F > 128) {
            float4 v = r[lane + 32];
            a1.x += w * v.x;  a1.y += w * v.y;  a1.z += w * v.z;  a1.w += w * v.w;
            if (lane < 12) {
                float4 t2 = r[lane + 64];
                a2.x += w * t2.x;  a2.y += w * t2.y;  a2.z += w * t2.z;  a2.w += w * t2.w;
            }
        }
    }
    float nd = g_nd[g][n];
    uint32_t* o = g_bufAh + (size_t)n * wstride;
    {
        uint32_t p0 = packbf(a0.x * nd, a0.y * nd);
        uint32_t p1 = packbf(a0.z * nd, a0.w * nd);
        *(uint2*)(o + 2 * lane) = make_uint2(p0, p1);
    }
    if (F > 128) {
        uint32_t p0 = packbf(a1.x * nd, a1.y * nd);
        uint32_t p1 = packbf(a1.z * nd, a1.w * nd);
        *(uint2*)(o + 64 + 2 * lane) = make_uint2(p0, p1);
        if (lane < 12) {
            uint32_t q0 = packbf(a2.x * nd, a2.y * nd);
            uint32_t q1 = packbf(a2.z * nd, a2.w * nd);
            *(uint2*)(o + 128 + 2 * lane) = make_uint2(q0, q1);
        } else if (lane < 16) {  // zero pad words 152..159
            *(uint2*)(o + 128 + 2 * lane) = make_uint2(0u, 0u);
        }
    }
}

// ---------------- bf16 mma.sync GEMM ----------------------------------------
// relu(bf16 A @ Wh^T + bias) -> g_bufB fp32, or (dosum) scalar sum only.
// CTA: 256 thr (8 warps 4x2), tile 128x64, BK=32 (16 bf16x2 words/chunk).
__device__ __forceinline__ void mma16(float* d, const uint32_t* a, const uint32_t* b) {
    asm volatile("mma.sync.aligned.m16n8k16.row.col.f32.bf16.bf16.f32 "
                 "{%0,%1,%2,%3}, {%4,%5,%6,%7}, {%8,%9}, {%0,%1,%2,%3};"
                 : "+f"(d[0]), "+f"(d[1]), "+f"(d[2]), "+f"(d[3])
                 : "r"(a[0]), "r"(a[1]), "r"(a[2]), "r"(a[3]),
                   "r"(b[0]), "r"(b[1]));
}

#define PADW 20  // 16 words + 4 pad

__global__ void __launch_bounds__(256)
k_gemm_mma(const float* __restrict__ bias, int wsel, int NC, int wstride, int dosum) {
    __shared__ uint32_t As[128][PADW];   // bf16x2 words along k
    __shared__ uint32_t Bs[64][PADW];
    __shared__ float wsum[8];

    const uint32_t* __restrict__ Wh = (wsel == 0) ? g_Wh1 : (wsel == 1) ? g_Wh2 : g_Wh3;
    const int Kp2 = NC * 16;

    int tid = threadIdx.x, wid = tid >> 5, lane = tid & 31;
    int wm = wid & 3, wn = wid >> 2;
    int rowBase = blockIdx.x * 128;
    int colBase = blockIdx.y * 64;

    float acc[2][4][4];
#pragma unroll
    for (int mi = 0; mi < 2; mi++)
#pragma unroll
        for (int ni = 0; ni < 4; ni++)
#pragma unroll
            for (int q = 0; q < 4; q++) acc[mi][ni][q] = 0.f;

    int ar = tid >> 2, aw = tid & 3;
    int br = tid >> 2, bw = tid & 3;
    uint4 aU[2], bU;

    {   // prefetch chunk 0
#pragma unroll
        for (int j = 0; j < 2; j++) {
            int gr = rowBase + ar + j * 64;
            aU[j] = (gr < NN)
                ? *(const uint4*)(g_bufAh + (size_t)gr * wstride + aw * 4)
                : make_uint4(0u, 0u, 0u, 0u);
        }
        bU = *(const uint4*)(Wh + (size_t)(colBase + br) * Kp2 + bw * 4);
    }

    for (int c = 0; c < NC; c++) {
#pragma unroll
        for (int j = 0; j < 2; j++)
            *(uint4*)&As[ar + j * 64][aw * 4] = aU[j];
        *(uint4*)&Bs[br][bw * 4] = bU;
        __syncthreads();

        if (c + 1 < NC) {
            int kw0 = (c + 1) * 16;
#pragma unroll
            for (int j = 0; j < 2; j++) {
                int gr = rowBase + ar + j * 64;
                aU[j] = (gr < NN)
                    ? *(const uint4*)(g_bufAh + (size_t)gr * wstride + kw0 + aw * 4)
                    : make_uint4(0u, 0u, 0u, 0u);
            }
            bU = *(const uint4*)(Wh + (size_t)(colBase + br) * Kp2 + kw0 + bw * 4);
        }

        int g = lane >> 2, cc = lane & 3;
#pragma unroll
        for (int kw = 0; kw < 16; kw += 8) {
            uint32_t af[2][4], bf[4][2];
#pragma unroll
            for (int mi = 0; mi < 2; mi++) {
                int base = wm * 32 + mi * 16 + g;
                af[mi][0] = As[base][kw + cc];
                af[mi][1] = As[base + 8][kw + cc];
                af[mi][2] = As[base][kw + cc + 4];
                af[mi][3] = As[base + 8][kw + cc + 4];
            }
#pragma unroll
            for (int ni = 0; ni < 4; ni++) {
                int nb = wn * 32 + ni * 8 + g;
                bf[ni][0] = Bs[nb][kw + cc];
                bf[ni][1] = Bs[nb][kw + cc + 4];
            }
#pragma unroll
            for (int mi = 0; mi < 2; mi++)
#pragma unroll
                for (int ni = 0; ni < 4; ni++)
                    mma16(acc[mi][ni], af[mi], bf[ni]);
        }
        __syncthreads();
    }

    // epilogue: bias + relu; store fp32 (layers 1-2) or scalar sum only (layer 3)
    float lsum = 0.f;
    int g = lane >> 2, cc = lane & 3;
#pragma unroll
    for (int mi = 0; mi < 2; mi++) {
        int r0 = rowBase + wm * 32 + mi * 16 + g;
#pragma unroll
        for (int ni = 0; ni < 4; ni++) {
            int c0 = colBase + wn * 32 + ni * 8 + cc * 2;
            if (c0 < FH) {
                float bz0 = bias[c0], bz1 = bias[c0 + 1];
                float v0 = fmaxf(acc[mi][ni][0] + bz0, 0.f);
                float v1 = fmaxf(acc[mi][ni][1] + bz1, 0.f);
                float v2 = fmaxf(acc[mi][ni][2] + bz0, 0.f);
                float v3 = fmaxf(acc[mi][ni][3] + bz1, 0.f);
                if (dosum) {
                    if (r0 < NN)     lsum += v0 + v1;
                    if (r0 + 8 < NN) lsum += v2 + v3;
                } else {
                    if (r0 < NN)
                        *(float2*)(g_bufB + (size_t)r0 * FH + c0) = make_float2(v0, v1);
                    if (r0 + 8 < NN)
                        *(float2*)(g_bufB + (size_t)(r0 + 8) * FH + c0) = make_float2(v2, v3);
                }
            }
        }
    }
    if (dosum) {
#pragma unroll
        for (int o = 16; o > 0; o >>= 1) lsum += __shfl_down_sync(0xffffffffu, lsum, o);
        if (lane == 0) wsum[wid] = lsum;
        __syncthreads();
        if (tid == 0) {
            double tot = 0.0;
#pragma unroll
            for (int w = 0; w < 8; w++) tot += (double)wsum[w];
            atomicAdd(&g_sum, tot);
        }
    }
}

__global__ void k_final(float* __restrict__ out) {
    out[0] = (float)(g_sum / (4.0 * NN * FH));
}

// ---------------- launch -----------------------------------------------------
extern "C" void kernel_launch(void* const* d_in, const int* in_sizes, int n_in,
                              void* d_out, int out_size) {
    const float* X[4];   int nx = 0;
    const int*   EDG[8]; int ne = 0;
    const float* W[3] = {0, 0, 0};
    const float* Bv[3]; int nb = 0;
    int nw2 = 0;
    for (int i = 0; i < n_in; i++) {
        int sz = in_sizes[i];
        if (sz == 6400000)      X[nx++]   = (const float*)d_in[i];
        else if (sz == 800000)  EDG[ne++] = (const int*)d_in[i];
        else if (sz == 38912)   W[0] = (const float*)d_in[i];
        else if (sz == 92416)   { W[1 + nw2] = (const float*)d_in[i]; nw2++; }
        else if (sz == 304)     Bv[nb++] = (const float*)d_in[i];
    }
    float* out = (float*)d_out;

    k_prep<<<480, 256>>>(W[0], W[1], W[2]);   // init + all weight preps

    // batched CSR build for all 4 graphs
    k_zero<<<dim3(NB, NG), 256>>>();
    k_deg<<<dim3(EE / 256, NG), 256>>>(EDG[0], EDG[1], EDG[2], EDG[3],
                                       EDG[4], EDG[5], EDG[6], EDG[7]);
    k_scan1<<<dim3(NB, NG), 256>>>();
    k_scan2<<<dim3(1, NG), 256>>>();
    k_scan3<<<dim3(NB, NG), 256>>>();
    k_scatter<<<dim3(EE / 256, NG), 256>>>(EDG[0], EDG[1], EDG[2], EDG[3],
                                           EDG[4], EDG[5], EDG[6], EDG[7]);

    dim3 gemmGrid((NN + 127) / 128, 5);  // N padded to 320
    const int spmmGrid = NN / 8;         // 6250 blocks x 8 warps
    for (int g = 0; g < 4; g++) {
        k_spmm<<<spmmGrid, 256>>>(X[g], 1, FI, g, 64);
        k_gemm_mma<<<gemmGrid, 256>>>(Bv[0], 0, 4, 64, 0);
        k_spmm<<<spmmGrid, 256>>>(X[g], 0, FH, g, 160);
        k_gemm_mma<<<gemmGrid, 256>>>(Bv[1], 1, 10, 160, 0);
        k_spmm<<<spmmGrid, 256>>>(X[g], 0, FH, g, 160);
        k_gemm_mma<<<gemmGrid, 256>>>(Bv[2], 2, 10, 160, 1);
    }
    k_final<<<1, 1>>>(out);
}

// round 16
// speedup vs baseline: 1.0910x; 1.0910x over previous
#include <cuda_runtime.h>
#include <cuda_bf16.h>
#include <math.h>
#include <stdint.h>

// GCN1: 3-layer GCN over 4 graphs, shared weights, scalar-mean output.
// R16: exact R11 baseline (best: 1348us) + ONE change: GEMM fragment loads
//      via ldmatrix.x4 (8 LDSM vs 48 scalar LDS per chunk-warp -- the GEMM
//      mainloop was smem-issue bound). SpMM untouched at its unroll-2
//      equilibrium (MLP increases regressed twice: R13, R15).

#define NN 50000
#define EE 800000
#define FH 304
#define FI 128
#define NG 4
#define NB 196   // ceil(NN/256)

// ---------------- scratch (__device__ only; never passed as kernel args) ----
__device__ __align__(128) uint32_t g_bufAh[(size_t)NN * 160]; // SpMM out bf16x2 (padded)
__device__ __align__(128) float    g_bufB[(size_t)NN * FH];   // GEMM out (fp32)
__device__ __align__(128) uint32_t g_Wh1[320 * 64];           // [Npad][K/2] bf16x2
__device__ __align__(128) uint32_t g_Wh2[320 * 160];
__device__ __align__(128) uint32_t g_Wh3[320 * 160];
__device__ float g_ns[NG][NN];
__device__ float g_nd[NG][NN];
__device__ int   g_deg_s[NG][NN];
__device__ int   g_deg_d[NG][NN];
__device__ int   g_rowoff[NG][NN + 1];
__device__ int   g_cursor[NG][NN];
__device__ int   g_csr[NG][EE];
__device__ int   g_bsum[NG][256];
__device__ int   g_boff[NG][256];
__device__ double g_sum;

// ---------------- helpers ----------------------------------------------------
__device__ __forceinline__ uint32_t packbf(float x, float y) {
    __nv_bfloat162 b = __float22bfloat162_rn(make_float2(x, y));
    return *(uint32_t*)&b;
}
__device__ __forceinline__ void ldmx4(uint32_t& r0, uint32_t& r1,
                                      uint32_t& r2, uint32_t& r3, uint32_t addr) {
    asm volatile("ldmatrix.sync.aligned.m8n8.x4.shared.b16 {%0,%1,%2,%3}, [%4];"
                 : "=r"(r0), "=r"(r1), "=r"(r2), "=r"(r3) : "r"(addr));
}

// ---------------- small kernels ---------------------------------------------
__global__ void k_init() { g_sum = 0.0; }

// W[K][FH] -> Wh[Npad=320][Kp/2] packed bf16x2, zero-padded
__global__ void k_prep_wh(const float* __restrict__ W, int sel, int K, int Kp2) {
    int id = blockIdx.x * blockDim.x + threadIdx.x;
    if (id >= 320 * Kp2) return;
    int n = id / Kp2, kw = id % Kp2;
    int k = 2 * kw;
    float v0 = (k < K && n < FH) ? W[(size_t)k * FH + n] : 0.f;
    float v1 = (k + 1 < K && n < FH) ? W[(size_t)(k + 1) * FH + n] : 0.f;
    uint32_t* dst = (sel == 0) ? g_Wh1 : (sel == 1) ? g_Wh2 : g_Wh3;
    dst[(size_t)n * Kp2 + kw] = packbf(v0, v1);
}

__global__ void k_zero() {
    int g = blockIdx.y;
    int i = blockIdx.x * blockDim.x + threadIdx.x;
    if (i < NN) { g_deg_s[g][i] = 0; g_deg_d[g][i] = 0; }
}

__global__ void k_deg(const int* __restrict__ s0, const int* __restrict__ d0,
                      const int* __restrict__ s1, const int* __restrict__ d1,
                      const int* __restrict__ s2, const int* __restrict__ d2,
                      const int* __restrict__ s3, const int* __restrict__ d3) {
    int g = blockIdx.y;
    const int* s = (g == 0) ? s0 : (g == 1) ? s1 : (g == 2) ? s2 : s3;
    const int* d = (g == 0) ? d0 : (g == 1) ? d1 : (g == 2) ? d2 : d3;
    int e = blockIdx.x * blockDim.x + threadIdx.x;
    if (e < EE) {
        atomicAdd(&g_deg_s[g][s[e]], 1);
        atomicAdd(&g_deg_d[g][d[e]], 1);
    }
}

__global__ void k_scan1() {
    int g = blockIdx.y, t = threadIdx.x;
    int i = blockIdx.x * 256 + t;
    __shared__ int sm[256];
    sm[t] = (i < NN) ? g_deg_d[g][i] : 0;
    __syncthreads();
    for (int o = 128; o > 0; o >>= 1) {
        if (t < o) sm[t] += sm[t + o];
        __syncthreads();
    }
    if (t == 0) g_bsum[g][blockIdx.x] = sm[0];
}

__global__ void k_scan2() {
    int g = blockIdx.y, t = threadIdx.x;
    int v = (t < NB) ? g_bsum[g][t] : 0;
    __shared__ int sm[256];
    sm[t] = v;
    __syncthreads();
    for (int o = 1; o < 256; o <<= 1) {
        int a = (t >= o) ? sm[t - o] : 0;
        __syncthreads();
        sm[t] += a;
        __syncthreads();
    }
    g_boff[g][t] = sm[t] - v;  // exclusive
}

__global__ void k_scan3() {
    int g = blockIdx.y, t = threadIdx.x;
    int i = blockIdx.x * 256 + t;
    int d = (i < NN) ? g_deg_d[g][i] : 0;
    __shared__ int sm[256];
    sm[t] = d;
    __syncthreads();
    for (int o = 1; o < 256; o <<= 1) {
        int a = (t >= o) ? sm[t - o] : 0;
        __syncthreads();
        sm[t] += a;
        __syncthreads();
    }
    int off = g_boff[g][blockIdx.x] + sm[t] - d;  // exclusive
    if (i < NN) {
        g_rowoff[g][i] = off;
        g_cursor[g][i] = off;
        g_nd[g][i] = rsqrtf((float)max(d, 1));
        g_ns[g][i] = rsqrtf((float)max(g_deg_s[g][i], 1));
    }
    if (blockIdx.x == 0 && t == 0) g_rowoff[g][NN] = EE;
}

__global__ void k_scatter(const int* __restrict__ s0, const int* __restrict__ d0,
                          const int* __restrict__ s1, const int* __restrict__ d1,
                          const int* __restrict__ s2, const int* __restrict__ d2,
                          const int* __restrict__ s3, const int* __restrict__ d3) {
    int g = blockIdx.y;
    const int* s = (g == 0) ? s0 : (g == 1) ? s1 : (g == 2) ? s2 : s3;
    const int* d = (g == 0) ? d0 : (g == 1) ? d1 : (g == 2) ? d2 : d3;
    int e = blockIdx.x * blockDim.x + threadIdx.x;
    if (e < EE) {
        int p = atomicAdd(&g_cursor[g][d[e]], 1);
        g_csr[g][p] = s[e];
    }
}

// Warp-per-dst SpMM, float4 gathers (fp32 rows), bf16x2 output (R11 form,
// unroll-2 equilibrium). Lane l owns float4 slots l, l+32 (F>128), l+64 (l<12).
__global__ void __launch_bounds__(256)
k_spmm(const float* __restrict__ xext, int use_ext, int F, int g, int wstride) {
    const float* __restrict__ hin = use_ext ? xext : (const float*)g_bufB;
    int n = blockIdx.x * 8 + (threadIdx.x >> 5);
    if (n >= NN) return;
    int lane = threadIdx.x & 31;
    int beg = g_rowoff[g][n];
    int end = g_rowoff[g][n + 1];
    float4 a0 = make_float4(0.f, 0.f, 0.f, 0.f);
    float4 a1 = make_float4(0.f, 0.f, 0.f, 0.f);
    float4 a2 = make_float4(0.f, 0.f, 0.f, 0.f);
    int j = beg;
    for (; j + 1 < end; j += 2) {
        int sA = g_csr[g][j], sB = g_csr[g][j + 1];       // broadcast loads
        float wA = g_ns[g][sA], wB = g_ns[g][sB];
        const float4* rA = (const float4*)(hin + (size_t)sA * F);
        const float4* rB = (const float4*)(hin + (size_t)sB * F);
        float4 uA = rA[lane], uB = rB[lane];
        a0.x += wA * uA.x + wB * uB.x;  a0.y += wA * uA.y + wB * uB.y;
        a0.z += wA * uA.z + wB * uB.z;  a0.w += wA * uA.w + wB * uB.w;
        if (F > 128) {
            float4 vA = rA[lane + 32], vB = rB[lane + 32];
            a1.x += wA * vA.x + wB * vB.x;  a1.y += wA * vA.y + wB * vB.y;
            a1.z += wA * vA.z + wB * vB.z;  a1.w += wA * vA.w + wB * vB.w;
            if (lane < 12) {
                float4 tA = rA[lane + 64], tB = rB[lane + 64];
                a2.x += wA * tA.x + wB * tB.x;  a2.y += wA * tA.y + wB * tB.y;
                a2.z += wA * tA.z + wB * tB.z;  a2.w += wA * tA.w + wB * tB.w;
            }
        }
    }
    if (j < end) {
        int s = g_csr[g][j];
        float w = g_ns[g][s];
        const float4* r = (const float4*)(hin + (size_t)s * F);
        float4 u = r[lane];
        a0.x += w * u.x;  a0.y += w * u.y;  a0.z += w * u.z;  a0.w += w * u.w;
        if (F > 128) {
            float4 v = r[lane + 32];
            a1.x += w * v.x;  a1.y += w * v.y;  a1.z += w * v.z;  a1.w += w * v.w;
            if (lane < 12) {
                float4 t2 = r[lane + 64];
                a2.x += w * t2.x;  a2.y += w * t2.y;  a2.z += w * t2.z;  a2.w += w * t2.w;
            }
        }
    }
    float nd = g_nd[g][n];
    uint32_t* o = g_bufAh + (size_t)n * wstride;
    {
        uint32_t p0 = packbf(a0.x * nd, a0.y * nd);
        uint32_t p1 = packbf(a0.z * nd, a0.w * nd);
        *(uint2*)(o + 2 * lane) = make_uint2(p0, p1);
    }
    if (F > 128) {
        uint32_t p0 = packbf(a1.x * nd, a1.y * nd);
        uint32_t p1 = packbf(a1.z * nd, a1.w * nd);
        *(uint2*)(o + 64 + 2 * lane) = make_uint2(p0, p1);
        if (lane < 12) {
            uint32_t q0 = packbf(a2.x * nd, a2.y * nd);
            uint32_t q1 = packbf(a2.z * nd, a2.w * nd);
            *(uint2*)(o + 128 + 2 * lane) = make_uint2(q0, q1);
        } else if (lane < 16) {  // zero pad words 152..159
            *(uint2*)(o + 128 + 2 * lane) = make_uint2(0u, 0u);
        }
    }
}

// ---------------- bf16 mma.sync GEMM (ldmatrix fragments) -------------------
// relu(bf16 A @ Wh^T + bias) -> g_bufB fp32, or (dosum) scalar sum only.
// CTA: 256 thr (8 warps 4x2), tile 128x64, BK=32 (16 bf16x2 words/chunk).
__device__ __forceinline__ void mma16(float* d, const uint32_t* a, const uint32_t* b) {
    asm volatile("mma.sync.aligned.m16n8k16.row.col.f32.bf16.bf16.f32 "
                 "{%0,%1,%2,%3}, {%4,%5,%6,%7}, {%8,%9}, {%0,%1,%2,%3};"
                 : "+f"(d[0]), "+f"(d[1]), "+f"(d[2]), "+f"(d[3])
                 : "r"(a[0]), "r"(a[1]), "r"(a[2]), "r"(a[3]),
                   "r"(b[0]), "r"(b[1]));
}

#define PADW 20  // 16 words + 4 pad; ldmatrix group banks: stride 20 mod 32 distinct

__global__ void __launch_bounds__(256)
k_gemm_mma(const float* __restrict__ bias, int wsel, int NC, int wstride, int dosum) {
    __shared__ uint32_t As[128][PADW];   // bf16x2 words along k
    __shared__ uint32_t Bs[64][PADW];
    __shared__ float wsum[8];

    const uint32_t* __restrict__ Wh = (wsel == 0) ? g_Wh1 : (wsel == 1) ? g_Wh2 : g_Wh3;
    const int Kp2 = NC * 16;

    int tid = threadIdx.x, wid = tid >> 5, lane = tid & 31;
    int wm = wid & 3, wn = wid >> 2;
    int rowBase = blockIdx.x * 128;
    int colBase = blockIdx.y * 64;

    float acc[2][4][4];
#pragma unroll
    for (int mi = 0; mi < 2; mi++)
#pragma unroll
        for (int ni = 0; ni < 4; ni++)
#pragma unroll
            for (int q = 0; q < 4; q++) acc[mi][ni][q] = 0.f;

    // ldmatrix source addresses (constant across chunks; kw adds bytes)
    // A tiles per (mi): lanes 0-7 rows base..+8 @kw; 8-15 rows base+8 @kw;
    //                   16-23 rows base @kw+4; 24-31 rows base+8 @kw+4
    // B tiles per (nip): lanes 0-7 n-rows ni0 @kw; 8-15 ni0 @kw+4;
    //                    16-23 ni1 @kw; 24-31 ni1 @kw+4
    int lg = lane >> 3, lr = lane & 7;
    uint32_t sAs = (uint32_t)__cvta_generic_to_shared(&As[0][0]);
    uint32_t sBs = (uint32_t)__cvta_generic_to_shared(&Bs[0][0]);
    uint32_t aAddr[2], bAddr[2];
#pragma unroll
    for (int mi = 0; mi < 2; mi++)
        aAddr[mi] = sAs + (((wm * 32 + mi * 16 + (lg & 1) * 8 + lr) * PADW
                            + (lg >> 1) * 4) << 2);
#pragma unroll
    for (int nip = 0; nip < 2; nip++)
        bAddr[nip] = sBs + (((wn * 32 + (nip * 2 + (lg >> 1)) * 8 + lr) * PADW
                             + (lg & 1) * 4) << 2);

    int ar = tid >> 2, aw = tid & 3;
    int br = tid >> 2, bw = tid & 3;
    uint4 aU[2], bU;

    {   // prefetch chunk 0
#pragma unroll
        for (int j = 0; j < 2; j++) {
            int gr = rowBase + ar + j * 64;
            aU[j] = (gr < NN)
                ? *(const uint4*)(g_bufAh + (size_t)gr * wstride + aw * 4)
                : make_uint4(0u, 0u, 0u, 0u);
        }
        bU = *(const uint4*)(Wh + (size_t)(colBase + br) * Kp2 + bw * 4);
    }

    for (int c = 0; c < NC; c++) {
#pragma unroll
        for (int j = 0; j < 2; j++)
            *(uint4*)&As[ar + j * 64][aw * 4] = aU[j];
        *(uint4*)&Bs[br][bw * 4] = bU;
        __syncthreads();

        if (c + 1 < NC) {
            int kw0 = (c + 1) * 16;
#pragma unroll
            for (int j = 0; j < 2; j++) {
                int gr = rowBase + ar + j * 64;
                aU[j] = (gr < NN)
                    ? *(const uint4*)(g_bufAh + (size_t)gr * wstride + kw0 + aw * 4)
                    : make_uint4(0u, 0u, 0u, 0u);
            }
            bU = *(const uint4*)(Wh + (size_t)(colBase + br) * Kp2 + kw0 + bw * 4);
        }

#pragma unroll
        for (int kw = 0; kw < 16; kw += 8) {
            uint32_t af[2][4], bf[4][2];
#pragma unroll
            for (int mi = 0; mi < 2; mi++)
                ldmx4(af[mi][0], af[mi][1], af[mi][2], af[mi][3],
                      aAddr[mi] + (kw << 2));
#pragma unroll
            for (int nip = 0; nip < 2; nip++)
                ldmx4(bf[nip * 2][0], bf[nip * 2][1],
                      bf[nip * 2 + 1][0], bf[nip * 2 + 1][1],
                      bAddr[nip] + (kw << 2));
#pragma unroll
            for (int mi = 0; mi < 2; mi++)
#pragma unroll
                for (int ni = 0; ni < 4; ni++)
                    mma16(acc[mi][ni], af[mi], bf[ni]);
        }
        __syncthreads();
    }

    // epilogue: bias + relu; store fp32 (layers 1-2) or scalar sum only (layer 3)
    float lsum = 0.f;
    int g = lane >> 2, cc = lane & 3;
#pragma unroll
    for (int mi = 0; mi < 2; mi++) {
        int r0 = rowBase + wm * 32 + mi * 16 + g;
#pragma unroll
        for (int ni = 0; ni < 4; ni++) {
            int c0 = colBase + wn * 32 + ni * 8 + cc * 2;
            if (c0 < FH) {
                float bz0 = bias[c0], bz1 = bias[c0 + 1];
                float v0 = fmaxf(acc[mi][ni][0] + bz0, 0.f);
                float v1 = fmaxf(acc[mi][ni][1] + bz1, 0.f);
                float v2 = fmaxf(acc[mi][ni][2] + bz0, 0.f);
                float v3 = fmaxf(acc[mi][ni][3] + bz1, 0.f);
                if (dosum) {
                    if (r0 < NN)     lsum += v0 + v1;
                    if (r0 + 8 < NN) lsum += v2 + v3;
                } else {
                    if (r0 < NN)
                        *(float2*)(g_bufB + (size_t)r0 * FH + c0) = make_float2(v0, v1);
                    if (r0 + 8 < NN)
                        *(float2*)(g_bufB + (size_t)(r0 + 8) * FH + c0) = make_float2(v2, v3);
                }
            }
        }
    }
    if (dosum) {
#pragma unroll
        for (int o = 16; o > 0; o >>= 1) lsum += __shfl_down_sync(0xffffffffu, lsum, o);
        if (lane == 0) wsum[wid] = lsum;
        __syncthreads();
        if (tid == 0) {
            double tot = 0.0;
#pragma unroll
            for (int w = 0; w < 8; w++) tot += (double)wsum[w];
            atomicAdd(&g_sum, tot);
        }
    }
}

__global__ void k_final(float* __restrict__ out) {
    out[0] = (float)(g_sum / (4.0 * NN * FH));
}

// ---------------- launch -----------------------------------------------------
extern "C" void kernel_launch(void* const* d_in, const int* in_sizes, int n_in,
                              void* d_out, int out_size) {
    const float* X[4];   int nx = 0;
    const int*   EDG[8]; int ne = 0;
    const float* W[3] = {0, 0, 0};
    const float* Bv[3]; int nb = 0;
    int nw2 = 0;
    for (int i = 0; i < n_in; i++) {
        int sz = in_sizes[i];
        if (sz == 6400000)      X[nx++]   = (const float*)d_in[i];
        else if (sz == 800000)  EDG[ne++] = (const int*)d_in[i];
        else if (sz == 38912)   W[0] = (const float*)d_in[i];
        else if (sz == 92416)   { W[1 + nw2] = (const float*)d_in[i]; nw2++; }
        else if (sz == 304)     Bv[nb++] = (const float*)d_in[i];
    }
    float* out = (float*)d_out;

    k_init<<<1, 1>>>();
    k_prep_wh<<<(320 * 64 + 255) / 256, 256>>>(W[0], 0, 128, 64);
    k_prep_wh<<<(320 * 160 + 255) / 256, 256>>>(W[1], 1, 304, 160);
    k_prep_wh<<<(320 * 160 + 255) / 256, 256>>>(W[2], 2, 304, 160);

    // batched CSR build for all 4 graphs
    k_zero<<<dim3(NB, NG), 256>>>();
    k_deg<<<dim3(EE / 256, NG), 256>>>(EDG[0], EDG[1], EDG[2], EDG[3],
                                       EDG[4], EDG[5], EDG[6], EDG[7]);
    k_scan1<<<dim3(NB, NG), 256>>>();
    k_scan2<<<dim3(1, NG), 256>>>();
    k_scan3<<<dim3(NB, NG), 256>>>();
    k_scatter<<<dim3(EE / 256, NG), 256>>>(EDG[0], EDG[1], EDG[2], EDG[3],
                                           EDG[4], EDG[5], EDG[6], EDG[7]);

    dim3 gemmGrid((NN + 127) / 128, 5);  // N padded to 320
    const int spmmGrid = NN / 8;         // 6250 blocks x 8 warps
    for (int g = 0; g < 4; g++) {
        k_spmm<<<spmmGrid, 256>>>(X[g], 1, FI, g, 64);
        k_gemm_mma<<<gemmGrid, 256>>>(Bv[0], 0, 4, 64, 0);
        k_spmm<<<spmmGrid, 256>>>(X[g], 0, FH, g, 160);
        k_gemm_mma<<<gemmGrid, 256>>>(Bv[1], 1, 10, 160, 0);
        k_spmm<<<spmmGrid, 256>>>(X[g], 0, FH, g, 160);
        k_gemm_mma<<<gemmGrid, 256>>>(Bv[2], 2, 10, 160, 1);
    }
    k_final<<<1, 1>>>(out);
}